// round 8
// baseline (speedup 1.0000x reference)
#include <cuda_runtime.h>
#include <cstdint>

// WeightedFeatureInteraction: out[b] = sum_{i<j} w[i,j] * <x[b,i,:], x[b,j,:]>
//   inputs [B, 64*128] fp32, field_weights [64,64] fp32, out [B,1] fp32.
//
// Round 7: R6 tf32 mma.sync Gram GEMM with cp.async (LDGSTS .cg) staging.
// 3 buffers/warp, depth-2 commit-group pipeline: issue chunk m+2, wait_group 2,
// compute chunk m. tf32 cvt moved after fragment LDS (same cvt count).
// Keeps R6's swizzled conflict-free smem layout and fragment mapping.

#define NF 64
#define ND 128
#define THREADS 256
#define WPC 8
#define NTILES 20
#define WBYTES (NTILES * 128 * 4)      // 10240: masked W fragments
#define CHUNK_BYTES 8192               // 64 rows x 32 cols fp32
#define SMEM_TOTAL (WBYTES + WPC * 3 * CHUNK_BYTES)   // 10240 + 196608

__device__ static const int TI[NTILES] = {0,0,0,0,0,0,0,0, 1,1,1,1,1,1, 2,2,2,2, 3,3};
__device__ static const int TJ[NTILES] = {0,1,2,3,4,5,6,7, 2,3,4,5,6,7, 4,5,6,7, 6,7};

__device__ __forceinline__ uint32_t cvt_tf32(uint32_t fbits) {
    uint32_t r;
    asm("cvt.rna.tf32.f32 %0, %1;" : "=r"(r) : "f"(__uint_as_float(fbits)));
    return r;
}

__device__ __forceinline__ void mma_tf32(float* d,
                                         uint32_t a0, uint32_t a1, uint32_t a2, uint32_t a3,
                                         uint32_t b0, uint32_t b1) {
    asm volatile("mma.sync.aligned.m16n8k8.row.col.f32.tf32.tf32.f32 "
                 "{%0,%1,%2,%3}, {%4,%5,%6,%7}, {%8,%9}, {%0,%1,%2,%3};"
                 : "+f"(d[0]), "+f"(d[1]), "+f"(d[2]), "+f"(d[3])
                 : "r"(a0), "r"(a1), "r"(a2), "r"(a3), "r"(b0), "r"(b1));
}

__device__ __forceinline__ uint32_t smem_u32(const void* p) {
    uint32_t a;
    asm("{ .reg .u64 t; cvta.to.shared.u64 t, %1; cvt.u32.u64 %0, t; }"
        : "=r"(a) : "l"(p));
    return a;
}

// Issue one 64x32 chunk as 16 cp.async.cg of 16B per lane into the swizzled
// buffer at dst_base; always commits a group (empty if b_m out of range).
__device__ __forceinline__ void issue_chunk(const float* __restrict__ x,
                                            int b_m, int B, int c,
                                            uint32_t dst_base, int lane) {
    if (b_m < B) {
        const int wrow = lane >> 3;
        const int wcol = (lane & 7) * 4;
        const float* src = x + (size_t)b_m * (NF * ND) + c * 32 + wcol;
#pragma unroll
        for (int u = 0; u < 16; ++u) {
            const int row = 4 * u + wrow;
            const uint32_t dst =
                dst_base + (uint32_t)(row * 32 + (wcol ^ ((row & 7) << 2))) * 4;
            const float* s = src + (size_t)row * ND;
            asm volatile("cp.async.cg.shared.global [%0], [%1], 16;"
                         :: "r"(dst), "l"(s) : "memory");
        }
    }
    asm volatile("cp.async.commit_group;" ::: "memory");
}

extern "C" __global__ void __launch_bounds__(THREADS, 1)
wfi_mma(const float* __restrict__ x, const float* __restrict__ fw,
        float* __restrict__ out, int B, int nwarps) {
    extern __shared__ char smem[];
    const int tid = threadIdx.x, wq = tid >> 5, lane = tid & 31;
    float* wsm = (float*)smem;

    // Masked W fragments in mma C-fragment layout.
    for (int idx = tid; idx < NTILES * 128; idx += THREADS) {
        int t = idx >> 7, rem = idx & 127, lp = rem >> 2, r = rem & 3;
        int i = TI[t] * 16 + (lp >> 2) + (r >> 1) * 8;
        int j = TJ[t] * 8 + (lp & 3) * 2 + (r & 1);
        wsm[idx] = (j > i) ? fw[i * NF + j] : 0.0f;
    }
    __syncthreads();

    const int b0 = blockIdx.x * WPC + wq;
    if (b0 >= B) return;

    // Per-warp triple buffer (byte addrs for cp.async, word ptrs for LDS).
    uint32_t bufa[3];
    const uint32_t* bufw[3];
#pragma unroll
    for (int r = 0; r < 3; ++r) {
        int off = WBYTES + (wq * 3 + r) * CHUNK_BYTES;
        bufa[r] = smem_u32(smem) + (uint32_t)off;
        bufw[r] = (const uint32_t*)(smem + off);
    }

    const int g  = lane >> 2;
    const int tg = lane & 3;

    // Prologue: chunks 0, 1 in flight.
    issue_chunk(x, b0, B, 0, bufa[0], lane);
    issue_chunk(x, b0 + ((1 >> 2) ? nwarps : 0), B, 1, bufa[1], lane);

    int m = 0;
    for (int b = b0; b < B; b += nwarps) {
        float acc[NTILES][4];
#pragma unroll
        for (int t = 0; t < NTILES; ++t)
#pragma unroll
            for (int r = 0; r < 4; ++r) acc[t][r] = 0.0f;

#pragma unroll 1
        for (int c = 0; c < 4; ++c, ++m) {
            const int m2 = m + 2;
            issue_chunk(x, b0 + (m2 >> 2) * nwarps, B, m2 & 3, bufa[m2 % 3], lane);
            asm volatile("cp.async.wait_group 2;" ::: "memory");
            __syncwarp();

            const uint32_t* buf = bufw[m % 3];
#pragma unroll
            for (int s = 0; s < 4; ++s) {
                uint32_t fx[8], fy[8];
#pragma unroll
                for (int r = 0; r < 8; ++r) {
                    const uint32_t base = (8 * r + g) * 32;
                    fx[r] = cvt_tf32(buf[base + ((8 * s + tg)     ^ (g << 2))]);
                    fy[r] = cvt_tf32(buf[base + ((8 * s + tg + 4) ^ (g << 2))]);
                }
#pragma unroll
                for (int t = 0; t < NTILES; ++t) {
                    const int ti = TI[t], tj = TJ[t];
                    mma_tf32(acc[t], fx[2 * ti], fx[2 * ti + 1],
                             fy[2 * ti], fy[2 * ti + 1], fx[tj], fy[tj]);
                }
            }
        }

        // Epilogue: weighted reduce of Gram fragments.
        float s = 0.0f;
#pragma unroll
        for (int t = 0; t < NTILES; ++t) {
            float4 w4 = *(const float4*)(wsm + (t * 32 + lane) * 4);
            s = fmaf(w4.x, acc[t][0], s);
            s = fmaf(w4.y, acc[t][1], s);
            s = fmaf(w4.z, acc[t][2], s);
            s = fmaf(w4.w, acc[t][3], s);
        }
#pragma unroll
        for (int off = 16; off > 0; off >>= 1)
            s += __shfl_xor_sync(0xFFFFFFFFu, s, off);
        if (lane == 0) out[b] = s;
    }
}

extern "C" void kernel_launch(void* const* d_in, const int* in_sizes, int n_in,
                              void* d_out, int out_size) {
    const float* x  = (const float*)d_in[0];
    const float* fw = (const float*)d_in[1];
    float* out      = (float*)d_out;

    int B = in_sizes[0] / (NF * ND);

    int dev = 0, nsm = 148;
    cudaGetDevice(&dev);
    cudaDeviceGetAttribute(&nsm, cudaDevAttrMultiProcessorCount, dev);

    cudaFuncSetAttribute(wfi_mma, cudaFuncAttributeMaxDynamicSharedMemorySize, SMEM_TOTAL);

    int grid = nsm;
    int nwarps = grid * WPC;
    wfi_mma<<<grid, THREADS, SMEM_TOTAL>>>(x, fw, out, B, nwarps);
}